// round 6
// baseline (speedup 1.0000x reference)
#include <cuda_runtime.h>
#include <math.h>

// ---------------------------------------------------------------------------
// Fused MHA forward, tf32 tensor cores (mma.sync.m16n8k8) with 3xTF32 split.
// Round 5: operands PRE-SPLIT into (hi,lo) float2 pairs in SMEM at tile-load
// time (split once, not per fragment read) -> no cvt/sub in mainloops.
// GEMMs double-buffered with register prefetch (1 sync / K-step).
// Attention: Q fragments hoisted to registers for the whole key loop.
// ---------------------------------------------------------------------------

#define D_MODEL 1024
#define NHEADS  16
#define HD      64
#define BATCH   2
#define SEQ     2048
#define MTOT    (BATCH * SEQ)

__device__ float g_q[BATCH * NHEADS * SEQ * HD];
__device__ float g_k[BATCH * NHEADS * SEQ * HD];
__device__ float g_v[BATCH * NHEADS * SEQ * HD];
__device__ float g_att[MTOT * D_MODEL];

__device__ __forceinline__ unsigned f2tf(float x) {
    unsigned r; asm("cvt.rna.tf32.f32 %0, %1;" : "=r"(r) : "f"(x)); return r;
}
__device__ __forceinline__ float2 split2(float x) {
    float hi = __uint_as_float(f2tf(x));
    float lo = __uint_as_float(f2tf(x - hi));
    return make_float2(hi, lo);
}
__device__ __forceinline__ void mma_tf32(float* d, const unsigned* a, const unsigned* b) {
    asm volatile(
        "mma.sync.aligned.m16n8k8.row.col.f32.tf32.tf32.f32 "
        "{%0,%1,%2,%3}, {%4,%5,%6,%7}, {%8,%9}, {%0,%1,%2,%3};\n"
        : "+f"(d[0]), "+f"(d[1]), "+f"(d[2]), "+f"(d[3])
        : "r"(a[0]), "r"(a[1]), "r"(a[2]), "r"(a[3]), "r"(b[0]), "r"(b[1]));
}

// Swizzles in float2-element space (and float space for Ps)
#define SW32_2(r, c) (((r) << 5) + ((c) ^ (((r) & 7) << 2)))
#define SW64_2(r, c) (((r) << 6) + ((c) ^ (((r) & 7) << 2)))
#define SW64F(r, c)  (((r) << 6) + ((c) ^ (((r) & 7) << 2)))

#define GEMM_SMEM ((2 * 128 * 32 + 2 * 64 * 32) * 8)   // 96 KB

// ---------------------------------------------------------------------------
// Projection GEMM body: CTA 128(M) x 64(N), K-step 32, 8 warps, warp 32x32.
// A,B pre-split hi/lo float2 in SMEM, double buffered, reg-prefetched.
// ---------------------------------------------------------------------------
struct GemmCtx {
    const float* A; const float* B; const float* bias;
    int bm, bn;
    int am, ak4, bkk, bn0;          // loader lane mapping
    int warp, g, tig, wm, wn;
};

__device__ __forceinline__ void gemm_ldg(const GemmCtx& c, int k0,
                                         float4 av[4], float bv8[8]) {
#pragma unroll
    for (int q = 0; q < 4; ++q)
        av[q] = *reinterpret_cast<const float4*>(
            c.A + (size_t)(c.bm + c.am) * D_MODEL + k0 + c.ak4 + q * 4);
#pragma unroll
    for (int j = 0; j < 8; ++j)
        bv8[j] = c.B[(size_t)(k0 + c.bkk) * D_MODEL + c.bn + c.bn0 + 8 * j];
}

__device__ __forceinline__ void gemm_sts(const GemmCtx& c, float2* As2, float2* Bs2,
                                         const float4 av[4], const float bv8[8]) {
#pragma unroll
    for (int q = 0; q < 4; ++q) {
        int c0 = c.ak4 + q * 4;
        float2 p0 = split2(av[q].x), p1 = split2(av[q].y);
        float2 p2 = split2(av[q].z), p3 = split2(av[q].w);
        *reinterpret_cast<float4*>(&As2[SW32_2(c.am, c0)])     = make_float4(p0.x, p0.y, p1.x, p1.y);
        *reinterpret_cast<float4*>(&As2[SW32_2(c.am, c0 + 2)]) = make_float4(p2.x, p2.y, p3.x, p3.y);
    }
#pragma unroll
    for (int j = 0; j < 8; ++j)
        Bs2[SW32_2(c.bn0 + 8 * j, c.bkk)] = split2(bv8[j]);
}

__device__ __forceinline__ void gemm_compute(const GemmCtx& c, const float2* As2,
                                             const float2* Bs2, float acc[2][4][4]) {
#pragma unroll
    for (int kk = 0; kk < 32; kk += 8) {
        unsigned ahi[2][4], alo[2][4];
#pragma unroll
        for (int t = 0; t < 2; ++t) {
            int r0 = c.wm + t * 16 + c.g;
            float2 a0 = As2[SW32_2(r0,     kk + c.tig)];
            float2 a1 = As2[SW32_2(r0 + 8, kk + c.tig)];
            float2 a2 = As2[SW32_2(r0,     kk + c.tig + 4)];
            float2 a3 = As2[SW32_2(r0 + 8, kk + c.tig + 4)];
            ahi[t][0] = __float_as_uint(a0.x); alo[t][0] = __float_as_uint(a0.y);
            ahi[t][1] = __float_as_uint(a1.x); alo[t][1] = __float_as_uint(a1.y);
            ahi[t][2] = __float_as_uint(a2.x); alo[t][2] = __float_as_uint(a2.y);
            ahi[t][3] = __float_as_uint(a3.x); alo[t][3] = __float_as_uint(a3.y);
        }
        unsigned bhi[4][2], blo[4][2];
#pragma unroll
        for (int u = 0; u < 4; ++u) {
            int n = c.wn + u * 8 + c.g;
            float2 b0 = Bs2[SW32_2(n, kk + c.tig)];
            float2 b1 = Bs2[SW32_2(n, kk + c.tig + 4)];
            bhi[u][0] = __float_as_uint(b0.x); blo[u][0] = __float_as_uint(b0.y);
            bhi[u][1] = __float_as_uint(b1.x); blo[u][1] = __float_as_uint(b1.y);
        }
#pragma unroll
        for (int t = 0; t < 2; ++t)
#pragma unroll
            for (int u = 0; u < 4; ++u) {
                mma_tf32(acc[t][u], ahi[t], bhi[u]);
                mma_tf32(acc[t][u], alo[t], bhi[u]);
                mma_tf32(acc[t][u], ahi[t], blo[u]);
            }
    }
}

__device__ __forceinline__ void gemm_main(GemmCtx& c, float acc[2][4][4], char* smempool) {
    float2* As2 = reinterpret_cast<float2*>(smempool);     // [2][4096]
    float2* Bs2 = As2 + 2 * 4096;                          // [2][2048]

    float4 av[4]; float bv8[8];
    gemm_ldg(c, 0, av, bv8);
    gemm_sts(c, As2, Bs2, av, bv8);
    __syncthreads();

    int cur = 0;
#pragma unroll 1
    for (int k0 = 0; k0 < D_MODEL; k0 += 32) {
        const bool more = (k0 + 32) < D_MODEL;
        if (more) gemm_ldg(c, k0 + 32, av, bv8);
        gemm_compute(c, As2 + cur * 4096, Bs2 + cur * 2048, acc);
        if (more) gemm_sts(c, As2 + (cur ^ 1) * 4096, Bs2 + (cur ^ 1) * 2048, av, bv8);
        __syncthreads();
        cur ^= 1;
    }
}

__device__ __forceinline__ void gemm_init_ctx(GemmCtx& c) {
    const int tid = threadIdx.x;
    const int lane = tid & 31;
    c.warp = tid >> 5;
    c.g = lane >> 2; c.tig = lane & 3;
    c.wm = (c.warp >> 1) * 32; c.wn = (c.warp & 1) * 32;
    c.am = tid >> 1; c.ak4 = (tid & 1) * 16;
    c.bkk = tid >> 3; c.bn0 = tid & 7;
}

// ---------------------------------------------------------------------------
__global__ __launch_bounds__(256, 2) void qkv_gemm(
    const float* __restrict__ x,
    const float* __restrict__ Wq, const float* __restrict__ bq,
    const float* __restrict__ Wk, const float* __restrict__ bk,
    const float* __restrict__ Wv, const float* __restrict__ bv)
{
    extern __shared__ char smempool[];
    GemmCtx c; gemm_init_ctx(c);
    c.A = x; c.bm = blockIdx.y * 128; c.bn = blockIdx.x * 64;
    float* outp;
    if (blockIdx.z == 0)      { c.B = Wq; c.bias = bq; outp = g_q; }
    else if (blockIdx.z == 1) { c.B = Wk; c.bias = bk; outp = g_k; }
    else                      { c.B = Wv; c.bias = bv; outp = g_v; }

    float acc[2][4][4] = {};
    gemm_main(c, acc, smempool);

    const int h = blockIdx.x;   // N-tile == HD
#pragma unroll
    for (int t = 0; t < 2; ++t)
#pragma unroll
        for (int u = 0; u < 4; ++u) {
            int dcol = c.wn + u * 8 + 2 * c.tig;
            float bx = c.bias[c.bn + dcol], by = c.bias[c.bn + dcol + 1];
            int m0 = c.bm + c.wm + t * 16 + c.g;
#pragma unroll
            for (int half = 0; half < 2; ++half) {
                int m = m0 + half * 8;
                int b_ = m >> 11, s_ = m & (SEQ - 1);
                float2 r;
                r.x = acc[t][u][half * 2 + 0] + bx;
                r.y = acc[t][u][half * 2 + 1] + by;
                *reinterpret_cast<float2*>(
                    outp + ((size_t)((b_ * NHEADS + h) * SEQ + s_)) * HD + dcol) = r;
            }
        }
}

__global__ __launch_bounds__(256, 2) void out_gemm(
    const float* __restrict__ Wo, const float* __restrict__ bo,
    float* __restrict__ out)
{
    extern __shared__ char smempool[];
    GemmCtx c; gemm_init_ctx(c);
    c.A = g_att; c.B = Wo; c.bias = bo;
    c.bm = blockIdx.y * 128; c.bn = blockIdx.x * 64;

    float acc[2][4][4] = {};
    gemm_main(c, acc, smempool);

#pragma unroll
    for (int t = 0; t < 2; ++t)
#pragma unroll
        for (int u = 0; u < 4; ++u) {
            int dcol = c.wn + u * 8 + 2 * c.tig;
            float bx = bo[c.bn + dcol], by = bo[c.bn + dcol + 1];
            int m0 = c.bm + c.wm + t * 16 + c.g;
#pragma unroll
            for (int half = 0; half < 2; ++half) {
                int m = m0 + half * 8;
                float2 r;
                r.x = acc[t][u][half * 2 + 0] + bx;
                r.y = acc[t][u][half * 2 + 1] + by;
                *reinterpret_cast<float2*>(out + (size_t)m * D_MODEL + c.bn + dcol) = r;
            }
        }
}

// ---------------------------------------------------------------------------
// Flash attention. CTA = 64 q-rows x (b,h), 4 warps x 16 q-rows.
// K/V pre-split (hi,lo) in SMEM; Q split once and held in registers all loop.
// QK^T: 3-mma split. PV: P single tf32 (A), V split (2 mma).
// SMEM: Ks2 32KB + Vt2 32KB + Ps 16KB = 80KB  (Q staged through Ks2).
// ---------------------------------------------------------------------------
#define ATTN_SMEM (80 * 1024)

__global__ __launch_bounds__(128, 2) void attn_kernel()
{
    extern __shared__ char smempool[];
    float2* Ks2 = reinterpret_cast<float2*>(smempool);   // [c][d] split
    float2* Vt2 = Ks2 + 4096;                            // [d][c] split
    float*  Ps  = reinterpret_cast<float*>(Vt2 + 4096);  // [q][c] SW64F

    const int tid  = threadIdx.x;
    const int warp = tid >> 5, lane = tid & 31;
    const int g = lane >> 2, tig = lane & 3;
    const int qw = warp * 16;
    const int bh = blockIdx.y;
    const int q0 = blockIdx.x * 64;

    const float* Qg = g_q + ((size_t)bh * SEQ + q0) * HD;
    const float* Kg = g_k + (size_t)bh * SEQ * HD;
    const float* Vg = g_v + (size_t)bh * SEQ * HD;
    const float scale = 0.125f;

    // Stage Q (scaled, split) through Ks2, then hoist fragments to registers.
#pragma unroll
    for (int it = 0; it < 8; ++it) {
        int idx = it * 128 + tid;
        int r = idx >> 4, c4 = (idx & 15) * 4;
        float4 v = *reinterpret_cast<const float4*>(Qg + r * HD + c4);
        float2 p0 = split2(v.x * scale), p1 = split2(v.y * scale);
        float2 p2 = split2(v.z * scale), p3 = split2(v.w * scale);
        *reinterpret_cast<float4*>(&Ks2[SW64_2(r, c4)])     = make_float4(p0.x, p0.y, p1.x, p1.y);
        *reinterpret_cast<float4*>(&Ks2[SW64_2(r, c4 + 2)]) = make_float4(p2.x, p2.y, p3.x, p3.y);
    }
    __syncthreads();

    unsigned qhi[8][4], qlo[8][4];
#pragma unroll
    for (int kk8 = 0; kk8 < 8; ++kk8) {
        int kk = kk8 * 8;
        float2 a0 = Ks2[SW64_2(qw + g,     kk + tig)];
        float2 a1 = Ks2[SW64_2(qw + g + 8, kk + tig)];
        float2 a2 = Ks2[SW64_2(qw + g,     kk + tig + 4)];
        float2 a3 = Ks2[SW64_2(qw + g + 8, kk + tig + 4)];
        qhi[kk8][0] = __float_as_uint(a0.x); qlo[kk8][0] = __float_as_uint(a0.y);
        qhi[kk8][1] = __float_as_uint(a1.x); qlo[kk8][1] = __float_as_uint(a1.y);
        qhi[kk8][2] = __float_as_uint(a2.x); qlo[kk8][2] = __float_as_uint(a2.y);
        qhi[kk8][3] = __float_as_uint(a3.x); qlo[kk8][3] = __float_as_uint(a3.y);
    }

    float o[8][4] = {};
    float mrow[2] = {-1e30f, -1e30f};
    float lrow[2] = {0.f, 0.f};

    for (int kt = 0; kt < SEQ / 64; ++kt) {
        const float* Kgt = Kg + kt * 64 * HD;
        const float* Vgt = Vg + kt * 64 * HD;

        __syncthreads();   // prev QK done with Ks2 (and Q-frag reads); prev PV done with Vt2/Ps
#pragma unroll
        for (int it = 0; it < 8; ++it) {
            int idx = it * 128 + tid;
            int r = idx >> 4, c4 = (idx & 15) * 4;
            float4 kv = *reinterpret_cast<const float4*>(Kgt + r * HD + c4);
            float2 k0s = split2(kv.x), k1s = split2(kv.y);
            float2 k2s = split2(kv.z), k3s = split2(kv.w);
            *reinterpret_cast<float4*>(&Ks2[SW64_2(r, c4)])     = make_float4(k0s.x, k0s.y, k1s.x, k1s.y);
            *reinterpret_cast<float4*>(&Ks2[SW64_2(r, c4 + 2)]) = make_float4(k2s.x, k2s.y, k3s.x, k3s.y);
            float4 vv = *reinterpret_cast<const float4*>(Vgt + r * HD + c4);
            Vt2[SW64_2(c4 + 0, r)] = split2(vv.x);   // transpose: Vt[d][c]
            Vt2[SW64_2(c4 + 1, r)] = split2(vv.y);
            Vt2[SW64_2(c4 + 2, r)] = split2(vv.z);
            Vt2[SW64_2(c4 + 3, r)] = split2(vv.w);
        }
        __syncthreads();

        // ---- scores: S = Q @ K^T (3-mma split) ----
        float s[8][4] = {};
#pragma unroll
        for (int kk8 = 0; kk8 < 8; ++kk8) {
            int kk = kk8 * 8;
#pragma unroll
            for (int u = 0; u < 8; ++u) {
                float2 b0 = Ks2[SW64_2(u * 8 + g, kk + tig)];
                float2 b1 = Ks2[SW64_2(u * 8 + g, kk + tig + 4)];
                unsigned bhi[2] = {__float_as_uint(b0.x), __float_as_uint(b1.x)};
                unsigned blo[2] = {__float_as_uint(b0.y), __float_as_uint(b1.y)};
                mma_tf32(s[u], qhi[kk8], bhi);
                mma_tf32(s[u], qlo[kk8], bhi);
                mma_tf32(s[u], qhi[kk8], blo);
            }
        }

        // ---- online softmax ----
        float mx0 = -1e30f, mx1 = -1e30f;
#pragma unroll
        for (int u = 0; u < 8; ++u) {
            mx0 = fmaxf(mx0, fmaxf(s[u][0], s[u][1]));
            mx1 = fmaxf(mx1, fmaxf(s[u][2], s[u][3]));
        }
        mx0 = fmaxf(mx0, __shfl_xor_sync(0xffffffffu, mx0, 1));
        mx0 = fmaxf(mx0, __shfl_xor_sync(0xffffffffu, mx0, 2));
        mx1 = fmaxf(mx1, __shfl_xor_sync(0xffffffffu, mx1, 1));
        mx1 = fmaxf(mx1, __shfl_xor_sync(0xffffffffu, mx1, 2));

        float m0n = fmaxf(mrow[0], mx0), m1n = fmaxf(mrow[1], mx1);
        float a0 = __expf(mrow[0] - m0n), a1 = __expf(mrow[1] - m1n);
        mrow[0] = m0n; mrow[1] = m1n;

        float rs0 = 0.f, rs1 = 0.f;
#pragma unroll
        for (int u = 0; u < 8; ++u) {
            s[u][0] = __expf(s[u][0] - m0n); rs0 += s[u][0];
            s[u][1] = __expf(s[u][1] - m0n); rs0 += s[u][1];
            s[u][2] = __expf(s[u][2] - m1n); rs1 += s[u][2];
            s[u][3] = __expf(s[u][3] - m1n); rs1 += s[u][3];
        }
        rs0 += __shfl_xor_sync(0xffffffffu, rs0, 1);
        rs0 += __shfl_xor_sync(0xffffffffu, rs0, 2);
        rs1 += __shfl_xor_sync(0xffffffffu, rs1, 1);
        rs1 += __shfl_xor_sync(0xffffffffu, rs1, 2);
        lrow[0] = lrow[0] * a0 + rs0;
        lrow[1] = lrow[1] * a1 + rs1;

#pragma unroll
        for (int u = 0; u < 8; ++u) {
            o[u][0] *= a0; o[u][1] *= a0; o[u][2] *= a1; o[u][3] *= a1;
            *reinterpret_cast<float2*>(&Ps[SW64F(qw + g,     u * 8 + 2 * tig)]) =
                make_float2(s[u][0], s[u][1]);
            *reinterpret_cast<float2*>(&Ps[SW64F(qw + g + 8, u * 8 + 2 * tig)]) =
                make_float2(s[u][2], s[u][3]);
        }
        __syncwarp();   // Ps rows are warp-private

        // ---- PV: O += P @ V (P single tf32, V split) ----
#pragma unroll
        for (int kk8 = 0; kk8 < 8; ++kk8) {
            int kk = kk8 * 8;
            unsigned pa[4];
            pa[0] = f2tf(Ps[SW64F(qw + g,     kk + tig)]);
            pa[1] = f2tf(Ps[SW64F(qw + g + 8, kk + tig)]);
            pa[2] = f2tf(Ps[SW64F(qw + g,     kk + tig + 4)]);
            pa[3] = f2tf(Ps[SW64F(qw + g + 8, kk + tig + 4)]);
#pragma unroll
            for (int u = 0; u < 8; ++u) {
                float2 b0 = Vt2[SW64_2(u * 8 + g, kk + tig)];
                float2 b1 = Vt2[SW64_2(u * 8 + g, kk + tig + 4)];
                unsigned vhi[2] = {__float_as_uint(b0.x), __float_as_uint(b1.x)};
                unsigned vlo[2] = {__float_as_uint(b0.y), __float_as_uint(b1.y)};
                mma_tf32(o[u], pa, vhi);
                mma_tf32(o[u], pa, vlo);
            }
        }
    }

    // Epilogue
    const int b_ = bh >> 4, h = bh & 15;
    const float inv0 = 1.0f / lrow[0], inv1 = 1.0f / lrow[1];
    const int r0 = q0 + qw + g, r1 = r0 + 8;
#pragma unroll
    for (int u = 0; u < 8; ++u) {
        int d = u * 8 + 2 * tig;
        *reinterpret_cast<float2*>(
            &g_att[((size_t)(b_ * SEQ + r0)) * D_MODEL + h * HD + d]) =
            make_float2(o[u][0] * inv0, o[u][1] * inv0);
        *reinterpret_cast<float2*>(
            &g_att[((size_t)(b_ * SEQ + r1)) * D_MODEL + h * HD + d]) =
            make_float2(o[u][2] * inv1, o[u][3] * inv1);
    }
}

// ---------------------------------------------------------------------------
extern "C" void kernel_launch(void* const* d_in, const int* in_sizes, int n_in,
                              void* d_out, int out_size)
{
    const float* x  = (const float*)d_in[0];
    const float* Wq = (const float*)d_in[1];
    const float* bq = (const float*)d_in[2];
    const float* Wk = (const float*)d_in[3];
    const float* bk = (const float*)d_in[4];
    const float* Wv = (const float*)d_in[5];
    const float* bv = (const float*)d_in[6];
    const float* Wo = (const float*)d_in[7];
    const float* bo = (const float*)d_in[8];
    float* out = (float*)d_out;

    cudaFuncSetAttribute(qkv_gemm, cudaFuncAttributeMaxDynamicSharedMemorySize, GEMM_SMEM);
    cudaFuncSetAttribute(out_gemm, cudaFuncAttributeMaxDynamicSharedMemorySize, GEMM_SMEM);
    cudaFuncSetAttribute(attn_kernel, cudaFuncAttributeMaxDynamicSharedMemorySize, ATTN_SMEM);

    dim3 g1(D_MODEL / 64, MTOT / 128, 3);
    qkv_gemm<<<g1, 256, GEMM_SMEM>>>(x, Wq, bq, Wk, bk, Wv, bv);

    dim3 g2(SEQ / 64, BATCH * NHEADS);
    attn_kernel<<<g2, 128, ATTN_SMEM>>>();

    dim3 g3(D_MODEL / 64, MTOT / 128);
    out_gemm<<<g3, 256, GEMM_SMEM>>>(Wo, bo, out);
}

// round 7
// speedup vs baseline: 1.0013x; 1.0013x over previous
#include <cuda_runtime.h>
#include <math.h>

// ---------------------------------------------------------------------------
// Fused MHA forward, tf32 tensor cores (mma.sync.m16n8k8) with 3xTF32 split.
// Round 5: operands PRE-SPLIT into (hi,lo) float2 pairs in SMEM at tile-load
// time (split once, not per fragment read) -> no cvt/sub in mainloops.
// GEMMs double-buffered with register prefetch (1 sync / K-step).
// Attention: Q fragments hoisted to registers for the whole key loop.
// ---------------------------------------------------------------------------

#define D_MODEL 1024
#define NHEADS  16
#define HD      64
#define BATCH   2
#define SEQ     2048
#define MTOT    (BATCH * SEQ)

__device__ float g_q[BATCH * NHEADS * SEQ * HD];
__device__ float g_k[BATCH * NHEADS * SEQ * HD];
__device__ float g_v[BATCH * NHEADS * SEQ * HD];
__device__ float g_att[MTOT * D_MODEL];

__device__ __forceinline__ unsigned f2tf(float x) {
    unsigned r; asm("cvt.rna.tf32.f32 %0, %1;" : "=r"(r) : "f"(x)); return r;
}
__device__ __forceinline__ float2 split2(float x) {
    float hi = __uint_as_float(f2tf(x));
    float lo = __uint_as_float(f2tf(x - hi));
    return make_float2(hi, lo);
}
__device__ __forceinline__ void mma_tf32(float* d, const unsigned* a, const unsigned* b) {
    asm volatile(
        "mma.sync.aligned.m16n8k8.row.col.f32.tf32.tf32.f32 "
        "{%0,%1,%2,%3}, {%4,%5,%6,%7}, {%8,%9}, {%0,%1,%2,%3};\n"
        : "+f"(d[0]), "+f"(d[1]), "+f"(d[2]), "+f"(d[3])
        : "r"(a[0]), "r"(a[1]), "r"(a[2]), "r"(a[3]), "r"(b[0]), "r"(b[1]));
}

// Swizzles in float2-element space (and float space for Ps)
#define SW32_2(r, c) (((r) << 5) + ((c) ^ (((r) & 7) << 2)))
#define SW64_2(r, c) (((r) << 6) + ((c) ^ (((r) & 7) << 2)))
#define SW64F(r, c)  (((r) << 6) + ((c) ^ (((r) & 7) << 2)))

#define GEMM_SMEM ((2 * 128 * 32 + 2 * 64 * 32) * 8)   // 96 KB

// ---------------------------------------------------------------------------
// Projection GEMM body: CTA 128(M) x 64(N), K-step 32, 8 warps, warp 32x32.
// A,B pre-split hi/lo float2 in SMEM, double buffered, reg-prefetched.
// ---------------------------------------------------------------------------
struct GemmCtx {
    const float* A; const float* B; const float* bias;
    int bm, bn;
    int am, ak4, bkk, bn0;          // loader lane mapping
    int warp, g, tig, wm, wn;
};

__device__ __forceinline__ void gemm_ldg(const GemmCtx& c, int k0,
                                         float4 av[4], float bv8[8]) {
#pragma unroll
    for (int q = 0; q < 4; ++q)
        av[q] = *reinterpret_cast<const float4*>(
            c.A + (size_t)(c.bm + c.am) * D_MODEL + k0 + c.ak4 + q * 4);
#pragma unroll
    for (int j = 0; j < 8; ++j)
        bv8[j] = c.B[(size_t)(k0 + c.bkk) * D_MODEL + c.bn + c.bn0 + 8 * j];
}

__device__ __forceinline__ void gemm_sts(const GemmCtx& c, float2* As2, float2* Bs2,
                                         const float4 av[4], const float bv8[8]) {
#pragma unroll
    for (int q = 0; q < 4; ++q) {
        int c0 = c.ak4 + q * 4;
        float2 p0 = split2(av[q].x), p1 = split2(av[q].y);
        float2 p2 = split2(av[q].z), p3 = split2(av[q].w);
        *reinterpret_cast<float4*>(&As2[SW32_2(c.am, c0)])     = make_float4(p0.x, p0.y, p1.x, p1.y);
        *reinterpret_cast<float4*>(&As2[SW32_2(c.am, c0 + 2)]) = make_float4(p2.x, p2.y, p3.x, p3.y);
    }
#pragma unroll
    for (int j = 0; j < 8; ++j)
        Bs2[SW32_2(c.bn0 + 8 * j, c.bkk)] = split2(bv8[j]);
}

__device__ __forceinline__ void gemm_compute(const GemmCtx& c, const float2* As2,
                                             const float2* Bs2, float acc[2][4][4]) {
#pragma unroll
    for (int kk = 0; kk < 32; kk += 8) {
        unsigned ahi[2][4], alo[2][4];
#pragma unroll
        for (int t = 0; t < 2; ++t) {
            int r0 = c.wm + t * 16 + c.g;
            float2 a0 = As2[SW32_2(r0,     kk + c.tig)];
            float2 a1 = As2[SW32_2(r0 + 8, kk + c.tig)];
            float2 a2 = As2[SW32_2(r0,     kk + c.tig + 4)];
            float2 a3 = As2[SW32_2(r0 + 8, kk + c.tig + 4)];
            ahi[t][0] = __float_as_uint(a0.x); alo[t][0] = __float_as_uint(a0.y);
            ahi[t][1] = __float_as_uint(a1.x); alo[t][1] = __float_as_uint(a1.y);
            ahi[t][2] = __float_as_uint(a2.x); alo[t][2] = __float_as_uint(a2.y);
            ahi[t][3] = __float_as_uint(a3.x); alo[t][3] = __float_as_uint(a3.y);
        }
        unsigned bhi[4][2], blo[4][2];
#pragma unroll
        for (int u = 0; u < 4; ++u) {
            int n = c.wn + u * 8 + c.g;
            float2 b0 = Bs2[SW32_2(n, kk + c.tig)];
            float2 b1 = Bs2[SW32_2(n, kk + c.tig + 4)];
            bhi[u][0] = __float_as_uint(b0.x); blo[u][0] = __float_as_uint(b0.y);
            bhi[u][1] = __float_as_uint(b1.x); blo[u][1] = __float_as_uint(b1.y);
        }
#pragma unroll
        for (int t = 0; t < 2; ++t)
#pragma unroll
            for (int u = 0; u < 4; ++u) {
                mma_tf32(acc[t][u], ahi[t], bhi[u]);
                mma_tf32(acc[t][u], alo[t], bhi[u]);
                mma_tf32(acc[t][u], ahi[t], blo[u]);
            }
    }
}

__device__ __forceinline__ void gemm_main(GemmCtx& c, float acc[2][4][4], char* smempool) {
    float2* As2 = reinterpret_cast<float2*>(smempool);     // [2][4096]
    float2* Bs2 = As2 + 2 * 4096;                          // [2][2048]

    float4 av[4]; float bv8[8];
    gemm_ldg(c, 0, av, bv8);
    gemm_sts(c, As2, Bs2, av, bv8);
    __syncthreads();

    int cur = 0;
#pragma unroll 1
    for (int k0 = 0; k0 < D_MODEL; k0 += 32) {
        const bool more = (k0 + 32) < D_MODEL;
        if (more) gemm_ldg(c, k0 + 32, av, bv8);
        gemm_compute(c, As2 + cur * 4096, Bs2 + cur * 2048, acc);
        if (more) gemm_sts(c, As2 + (cur ^ 1) * 4096, Bs2 + (cur ^ 1) * 2048, av, bv8);
        __syncthreads();
        cur ^= 1;
    }
}

__device__ __forceinline__ void gemm_init_ctx(GemmCtx& c) {
    const int tid = threadIdx.x;
    const int lane = tid & 31;
    c.warp = tid >> 5;
    c.g = lane >> 2; c.tig = lane & 3;
    c.wm = (c.warp >> 1) * 32; c.wn = (c.warp & 1) * 32;
    c.am = tid >> 1; c.ak4 = (tid & 1) * 16;
    c.bkk = tid >> 3; c.bn0 = tid & 7;
}

// ---------------------------------------------------------------------------
__global__ __launch_bounds__(256, 2) void qkv_gemm(
    const float* __restrict__ x,
    const float* __restrict__ Wq, const float* __restrict__ bq,
    const float* __restrict__ Wk, const float* __restrict__ bk,
    const float* __restrict__ Wv, const float* __restrict__ bv)
{
    extern __shared__ char smempool[];
    GemmCtx c; gemm_init_ctx(c);
    c.A = x; c.bm = blockIdx.y * 128; c.bn = blockIdx.x * 64;
    float* outp;
    if (blockIdx.z == 0)      { c.B = Wq; c.bias = bq; outp = g_q; }
    else if (blockIdx.z == 1) { c.B = Wk; c.bias = bk; outp = g_k; }
    else                      { c.B = Wv; c.bias = bv; outp = g_v; }

    float acc[2][4][4] = {};
    gemm_main(c, acc, smempool);

    const int h = blockIdx.x;   // N-tile == HD
#pragma unroll
    for (int t = 0; t < 2; ++t)
#pragma unroll
        for (int u = 0; u < 4; ++u) {
            int dcol = c.wn + u * 8 + 2 * c.tig;
            float bx = c.bias[c.bn + dcol], by = c.bias[c.bn + dcol + 1];
            int m0 = c.bm + c.wm + t * 16 + c.g;
#pragma unroll
            for (int half = 0; half < 2; ++half) {
                int m = m0 + half * 8;
                int b_ = m >> 11, s_ = m & (SEQ - 1);
                float2 r;
                r.x = acc[t][u][half * 2 + 0] + bx;
                r.y = acc[t][u][half * 2 + 1] + by;
                *reinterpret_cast<float2*>(
                    outp + ((size_t)((b_ * NHEADS + h) * SEQ + s_)) * HD + dcol) = r;
            }
        }
}

__global__ __launch_bounds__(256, 2) void out_gemm(
    const float* __restrict__ Wo, const float* __restrict__ bo,
    float* __restrict__ out)
{
    extern __shared__ char smempool[];
    GemmCtx c; gemm_init_ctx(c);
    c.A = g_att; c.B = Wo; c.bias = bo;
    c.bm = blockIdx.y * 128; c.bn = blockIdx.x * 64;

    float acc[2][4][4] = {};
    gemm_main(c, acc, smempool);

#pragma unroll
    for (int t = 0; t < 2; ++t)
#pragma unroll
        for (int u = 0; u < 4; ++u) {
            int dcol = c.wn + u * 8 + 2 * c.tig;
            float bx = bo[c.bn + dcol], by = bo[c.bn + dcol + 1];
            int m0 = c.bm + c.wm + t * 16 + c.g;
#pragma unroll
            for (int half = 0; half < 2; ++half) {
                int m = m0 + half * 8;
                float2 r;
                r.x = acc[t][u][half * 2 + 0] + bx;
                r.y = acc[t][u][half * 2 + 1] + by;
                *reinterpret_cast<float2*>(out + (size_t)m * D_MODEL + c.bn + dcol) = r;
            }
        }
}

// ---------------------------------------------------------------------------
// Flash attention. CTA = 64 q-rows x (b,h), 4 warps x 16 q-rows.
// K/V pre-split (hi,lo) in SMEM; Q split once and held in registers all loop.
// QK^T: 3-mma split. PV: P single tf32 (A), V split (2 mma).
// SMEM: Ks2 32KB + Vt2 32KB + Ps 16KB = 80KB  (Q staged through Ks2).
// ---------------------------------------------------------------------------
#define ATTN_SMEM (80 * 1024)

__global__ __launch_bounds__(128, 2) void attn_kernel()
{
    extern __shared__ char smempool[];
    float2* Ks2 = reinterpret_cast<float2*>(smempool);   // [c][d] split
    float2* Vt2 = Ks2 + 4096;                            // [d][c] split
    float*  Ps  = reinterpret_cast<float*>(Vt2 + 4096);  // [q][c] SW64F

    const int tid  = threadIdx.x;
    const int warp = tid >> 5, lane = tid & 31;
    const int g = lane >> 2, tig = lane & 3;
    const int qw = warp * 16;
    const int bh = blockIdx.y;
    const int q0 = blockIdx.x * 64;

    const float* Qg = g_q + ((size_t)bh * SEQ + q0) * HD;
    const float* Kg = g_k + (size_t)bh * SEQ * HD;
    const float* Vg = g_v + (size_t)bh * SEQ * HD;
    const float scale = 0.125f;

    // Stage Q (scaled, split) through Ks2, then hoist fragments to registers.
#pragma unroll
    for (int it = 0; it < 8; ++it) {
        int idx = it * 128 + tid;
        int r = idx >> 4, c4 = (idx & 15) * 4;
        float4 v = *reinterpret_cast<const float4*>(Qg + r * HD + c4);
        float2 p0 = split2(v.x * scale), p1 = split2(v.y * scale);
        float2 p2 = split2(v.z * scale), p3 = split2(v.w * scale);
        *reinterpret_cast<float4*>(&Ks2[SW64_2(r, c4)])     = make_float4(p0.x, p0.y, p1.x, p1.y);
        *reinterpret_cast<float4*>(&Ks2[SW64_2(r, c4 + 2)]) = make_float4(p2.x, p2.y, p3.x, p3.y);
    }
    __syncthreads();

    unsigned qhi[8][4], qlo[8][4];
#pragma unroll
    for (int kk8 = 0; kk8 < 8; ++kk8) {
        int kk = kk8 * 8;
        float2 a0 = Ks2[SW64_2(qw + g,     kk + tig)];
        float2 a1 = Ks2[SW64_2(qw + g + 8, kk + tig)];
        float2 a2 = Ks2[SW64_2(qw + g,     kk + tig + 4)];
        float2 a3 = Ks2[SW64_2(qw + g + 8, kk + tig + 4)];
        qhi[kk8][0] = __float_as_uint(a0.x); qlo[kk8][0] = __float_as_uint(a0.y);
        qhi[kk8][1] = __float_as_uint(a1.x); qlo[kk8][1] = __float_as_uint(a1.y);
        qhi[kk8][2] = __float_as_uint(a2.x); qlo[kk8][2] = __float_as_uint(a2.y);
        qhi[kk8][3] = __float_as_uint(a3.x); qlo[kk8][3] = __float_as_uint(a3.y);
    }

    float o[8][4] = {};
    float mrow[2] = {-1e30f, -1e30f};
    float lrow[2] = {0.f, 0.f};

    for (int kt = 0; kt < SEQ / 64; ++kt) {
        const float* Kgt = Kg + kt * 64 * HD;
        const float* Vgt = Vg + kt * 64 * HD;

        __syncthreads();   // prev QK done with Ks2 (and Q-frag reads); prev PV done with Vt2/Ps
#pragma unroll
        for (int it = 0; it < 8; ++it) {
            int idx = it * 128 + tid;
            int r = idx >> 4, c4 = (idx & 15) * 4;
            float4 kv = *reinterpret_cast<const float4*>(Kgt + r * HD + c4);
            float2 k0s = split2(kv.x), k1s = split2(kv.y);
            float2 k2s = split2(kv.z), k3s = split2(kv.w);
            *reinterpret_cast<float4*>(&Ks2[SW64_2(r, c4)])     = make_float4(k0s.x, k0s.y, k1s.x, k1s.y);
            *reinterpret_cast<float4*>(&Ks2[SW64_2(r, c4 + 2)]) = make_float4(k2s.x, k2s.y, k3s.x, k3s.y);
            float4 vv = *reinterpret_cast<const float4*>(Vgt + r * HD + c4);
            Vt2[SW64_2(c4 + 0, r)] = split2(vv.x);   // transpose: Vt[d][c]
            Vt2[SW64_2(c4 + 1, r)] = split2(vv.y);
            Vt2[SW64_2(c4 + 2, r)] = split2(vv.z);
            Vt2[SW64_2(c4 + 3, r)] = split2(vv.w);
        }
        __syncthreads();

        // ---- scores: S = Q @ K^T (3-mma split) ----
        float s[8][4] = {};
#pragma unroll
        for (int kk8 = 0; kk8 < 8; ++kk8) {
            int kk = kk8 * 8;
#pragma unroll
            for (int u = 0; u < 8; ++u) {
                float2 b0 = Ks2[SW64_2(u * 8 + g, kk + tig)];
                float2 b1 = Ks2[SW64_2(u * 8 + g, kk + tig + 4)];
                unsigned bhi[2] = {__float_as_uint(b0.x), __float_as_uint(b1.x)};
                unsigned blo[2] = {__float_as_uint(b0.y), __float_as_uint(b1.y)};
                mma_tf32(s[u], qhi[kk8], bhi);
                mma_tf32(s[u], qlo[kk8], bhi);
                mma_tf32(s[u], qhi[kk8], blo);
            }
        }

        // ---- online softmax ----
        float mx0 = -1e30f, mx1 = -1e30f;
#pragma unroll
        for (int u = 0; u < 8; ++u) {
            mx0 = fmaxf(mx0, fmaxf(s[u][0], s[u][1]));
            mx1 = fmaxf(mx1, fmaxf(s[u][2], s[u][3]));
        }
        mx0 = fmaxf(mx0, __shfl_xor_sync(0xffffffffu, mx0, 1));
        mx0 = fmaxf(mx0, __shfl_xor_sync(0xffffffffu, mx0, 2));
        mx1 = fmaxf(mx1, __shfl_xor_sync(0xffffffffu, mx1, 1));
        mx1 = fmaxf(mx1, __shfl_xor_sync(0xffffffffu, mx1, 2));

        float m0n = fmaxf(mrow[0], mx0), m1n = fmaxf(mrow[1], mx1);
        float a0 = __expf(mrow[0] - m0n), a1 = __expf(mrow[1] - m1n);
        mrow[0] = m0n; mrow[1] = m1n;

        float rs0 = 0.f, rs1 = 0.f;
#pragma unroll
        for (int u = 0; u < 8; ++u) {
            s[u][0] = __expf(s[u][0] - m0n); rs0 += s[u][0];
            s[u][1] = __expf(s[u][1] - m0n); rs0 += s[u][1];
            s[u][2] = __expf(s[u][2] - m1n); rs1 += s[u][2];
            s[u][3] = __expf(s[u][3] - m1n); rs1 += s[u][3];
        }
        rs0 += __shfl_xor_sync(0xffffffffu, rs0, 1);
        rs0 += __shfl_xor_sync(0xffffffffu, rs0, 2);
        rs1 += __shfl_xor_sync(0xffffffffu, rs1, 1);
        rs1 += __shfl_xor_sync(0xffffffffu, rs1, 2);
        lrow[0] = lrow[0] * a0 + rs0;
        lrow[1] = lrow[1] * a1 + rs1;

#pragma unroll
        for (int u = 0; u < 8; ++u) {
            o[u][0] *= a0; o[u][1] *= a0; o[u][2] *= a1; o[u][3] *= a1;
            *reinterpret_cast<float2*>(&Ps[SW64F(qw + g,     u * 8 + 2 * tig)]) =
                make_float2(s[u][0], s[u][1]);
            *reinterpret_cast<float2*>(&Ps[SW64F(qw + g + 8, u * 8 + 2 * tig)]) =
                make_float2(s[u][2], s[u][3]);
        }
        __syncwarp();   // Ps rows are warp-private

        // ---- PV: O += P @ V (P single tf32, V split) ----
#pragma unroll
        for (int kk8 = 0; kk8 < 8; ++kk8) {
            int kk = kk8 * 8;
            unsigned pa[4];
            pa[0] = f2tf(Ps[SW64F(qw + g,     kk + tig)]);
            pa[1] = f2tf(Ps[SW64F(qw + g + 8, kk + tig)]);
            pa[2] = f2tf(Ps[SW64F(qw + g,     kk + tig + 4)]);
            pa[3] = f2tf(Ps[SW64F(qw + g + 8, kk + tig + 4)]);
#pragma unroll
            for (int u = 0; u < 8; ++u) {
                float2 b0 = Vt2[SW64_2(u * 8 + g, kk + tig)];
                float2 b1 = Vt2[SW64_2(u * 8 + g, kk + tig + 4)];
                unsigned vhi[2] = {__float_as_uint(b0.x), __float_as_uint(b1.x)};
                unsigned vlo[2] = {__float_as_uint(b0.y), __float_as_uint(b1.y)};
                mma_tf32(o[u], pa, vhi);
                mma_tf32(o[u], pa, vlo);
            }
        }
    }

    // Epilogue
    const int b_ = bh >> 4, h = bh & 15;
    const float inv0 = 1.0f / lrow[0], inv1 = 1.0f / lrow[1];
    const int r0 = q0 + qw + g, r1 = r0 + 8;
#pragma unroll
    for (int u = 0; u < 8; ++u) {
        int d = u * 8 + 2 * tig;
        *reinterpret_cast<float2*>(
            &g_att[((size_t)(b_ * SEQ + r0)) * D_MODEL + h * HD + d]) =
            make_float2(o[u][0] * inv0, o[u][1] * inv0);
        *reinterpret_cast<float2*>(
            &g_att[((size_t)(b_ * SEQ + r1)) * D_MODEL + h * HD + d]) =
            make_float2(o[u][2] * inv1, o[u][3] * inv1);
    }
}

// ---------------------------------------------------------------------------
extern "C" void kernel_launch(void* const* d_in, const int* in_sizes, int n_in,
                              void* d_out, int out_size)
{
    const float* x  = (const float*)d_in[0];
    const float* Wq = (const float*)d_in[1];
    const float* bq = (const float*)d_in[2];
    const float* Wk = (const float*)d_in[3];
    const float* bk = (const float*)d_in[4];
    const float* Wv = (const float*)d_in[5];
    const float* bv = (const float*)d_in[6];
    const float* Wo = (const float*)d_in[7];
    const float* bo = (const float*)d_in[8];
    float* out = (float*)d_out;

    cudaFuncSetAttribute(qkv_gemm, cudaFuncAttributeMaxDynamicSharedMemorySize, GEMM_SMEM);
    cudaFuncSetAttribute(out_gemm, cudaFuncAttributeMaxDynamicSharedMemorySize, GEMM_SMEM);
    cudaFuncSetAttribute(attn_kernel, cudaFuncAttributeMaxDynamicSharedMemorySize, ATTN_SMEM);

    dim3 g1(D_MODEL / 64, MTOT / 128, 3);
    qkv_gemm<<<g1, 256, GEMM_SMEM>>>(x, Wq, bq, Wk, bk, Wv, bv);

    dim3 g2(SEQ / 64, BATCH * NHEADS);
    attn_kernel<<<g2, 128, ATTN_SMEM>>>();

    dim3 g3(D_MODEL / 64, MTOT / 128);
    out_gemm<<<g3, 256, GEMM_SMEM>>>(Wo, bo, out);
}

// round 8
// speedup vs baseline: 2.5897x; 2.5863x over previous
#include <cuda_runtime.h>
#include <math.h>

// ---------------------------------------------------------------------------
// Fused MHA forward on bf16 tensor cores (mma.sync.m16n8k16) with hi/lo
// split-bf16 (3-term) error compensation everywhere.
// B=2, S=2048, D=1024, H=16, Hd=64, fp32 in/out.
// Key ideas vs tf32 rounds:
//  - (hi,lo) bf16 pair packed in one 32-bit word = same footprint as fp32,
//    fragments load with plain LDS.32, zero cvt in mainloops.
//  - k16 mma: half the tensor instructions of tf32 k8 at same accuracy class.
//  - Producers write pre-split operands (Q/K/V from qkv_gemm, attended from
//    attention) so consumers never convert.
//  - Attention: P stays in registers (fragment layout matches softmax regs);
//    V via ldmatrix.x4.trans.b16 on a 16B-XOR swizzled [c][d] tile.
// ---------------------------------------------------------------------------

#define D_MODEL 1024
#define NHEADS  16
#define HD      64
#define BATCH   2
#define SEQ     2048
#define MTOT    (BATCH * SEQ)
#define BHS     (BATCH * NHEADS * SEQ)

// Scratch: packed bf16x2 words. [b,h,s,dp] dp = d/2 (32 words per row of 64).
__device__ unsigned g_qhi[BHS * 32], g_qlo[BHS * 32];
__device__ unsigned g_khi[BHS * 32], g_klo[BHS * 32];
__device__ unsigned g_vhi[BHS * 32], g_vlo[BHS * 32];   // semantic: bf16[c][64]
// attended, packed over model dim: [m][kp], kp = k/2 (512 words per row)
__device__ unsigned g_ahi[MTOT * 512], g_alo[MTOT * 512];

// pack2(e,o): bf16x2 word, low half = e (even k), high half = o (odd k)
__device__ __forceinline__ unsigned pack2(float e, float o) {
    unsigned d;
    asm("cvt.rn.bf16x2.f32 %0, %1, %2;" : "=r"(d) : "f"(o), "f"(e));
    return d;
}
__device__ __forceinline__ void split_pack(float e, float o, unsigned& hi, unsigned& lo) {
    hi = pack2(e, o);
    float he = __uint_as_float(hi << 16);
    float ho = __uint_as_float(hi & 0xFFFF0000u);
    lo = pack2(e - he, o - ho);
}
__device__ __forceinline__ void mma_bf16(float* d, const unsigned* a, const unsigned* b) {
    asm volatile(
        "mma.sync.aligned.m16n8k16.row.col.f32.bf16.bf16.f32 "
        "{%0,%1,%2,%3}, {%4,%5,%6,%7}, {%8,%9}, {%0,%1,%2,%3};\n"
        : "+f"(d[0]), "+f"(d[1]), "+f"(d[2]), "+f"(d[3])
        : "r"(a[0]), "r"(a[1]), "r"(a[2]), "r"(a[3]), "r"(b[0]), "r"(b[1]));
}
__device__ __forceinline__ void ldsm_x4_t(unsigned& r0, unsigned& r1,
                                          unsigned& r2, unsigned& r3, unsigned addr) {
    asm volatile("ldmatrix.sync.aligned.m8n8.x4.trans.shared.b16 {%0,%1,%2,%3}, [%4];"
                 : "=r"(r0), "=r"(r1), "=r"(r2), "=r"(r3) : "r"(addr));
}

// Bank-conflict-free swizzles (word granularity).
// 16 words/row (GEMM tiles): rows r..r+7 x quad -> 32 distinct banks.
#define IDXA(r, dp) (((r) << 4) + ((dp) ^ ((((r) >> 1) & 3) << 2)))
// 32 words/row (attention K/V tiles)
#define IDXK(r, dp) (((r) << 5) + ((dp) ^ (((r) & 7) << 2)))

// ---------------------------------------------------------------------------
// QKV projection: CTA 128(M) x 64(N), K-step 32 (= 2 x k16 mma), 8 warps.
// Writes split-head PACKED hi/lo outputs (Q pre-scaled by 1/8).
// ---------------------------------------------------------------------------
__global__ __launch_bounds__(256) void qkv_gemm(
    const float* __restrict__ x,
    const float* __restrict__ Wq, const float* __restrict__ bq,
    const float* __restrict__ Wk, const float* __restrict__ bk,
    const float* __restrict__ Wv, const float* __restrict__ bv)
{
    __shared__ unsigned Ahi[128 * 16], Alo[128 * 16];
    __shared__ unsigned Bhi[64 * 16],  Blo[64 * 16];

    const float* W; const float* bias; unsigned* outHi; unsigned* outLo;
    bool isQ = false;
    if (blockIdx.z == 0)      { W = Wq; bias = bq; outHi = g_qhi; outLo = g_qlo; isQ = true; }
    else if (blockIdx.z == 1) { W = Wk; bias = bk; outHi = g_khi; outLo = g_klo; }
    else                      { W = Wv; bias = bv; outHi = g_vhi; outLo = g_vlo; }

    const int tid  = threadIdx.x;
    const int warp = tid >> 5, lane = tid & 31;
    const int g = lane >> 2, tig = lane & 3;
    const int wm = (warp >> 1) * 32, wn = (warp & 1) * 32;
    const int bm = blockIdx.y * 128, bn = blockIdx.x * 64;

    const int am  = tid >> 1;            // A row 0..127
    const int af  = (tid & 1) * 16;      // A float col base
    const int dpb = (tid & 1) * 8;       // A dp base
    const int kp  = tid & 15;            // B k-pair 0..15
    const int n4  = (tid >> 4) * 4;      // B n base

    float acc[2][4][4] = {};

#pragma unroll 1
    for (int k0 = 0; k0 < D_MODEL; k0 += 32) {
        float4 av[4];
#pragma unroll
        for (int q = 0; q < 4; ++q)
            av[q] = *reinterpret_cast<const float4*>(
                x + (size_t)(bm + am) * D_MODEL + k0 + af + q * 4);
        float4 b0 = *reinterpret_cast<const float4*>(W + (size_t)(k0 + 2 * kp) * D_MODEL + bn + n4);
        float4 b1 = *reinterpret_cast<const float4*>(W + (size_t)(k0 + 2 * kp + 1) * D_MODEL + bn + n4);

        __syncthreads();
#pragma unroll
        for (int q = 0; q < 4; ++q) {
            unsigned h0, l0, h1, l1;
            split_pack(av[q].x, av[q].y, h0, l0);
            split_pack(av[q].z, av[q].w, h1, l1);
            int ia = IDXA(am, dpb + 2 * q);       // even dp, pair-contiguous
            *reinterpret_cast<uint2*>(&Ahi[ia]) = make_uint2(h0, h1);
            *reinterpret_cast<uint2*>(&Alo[ia]) = make_uint2(l0, l1);
        }
        {
            const float* f0 = reinterpret_cast<const float*>(&b0);
            const float* f1 = reinterpret_cast<const float*>(&b1);
#pragma unroll
            for (int j = 0; j < 4; ++j) {
                unsigned h, l;
                split_pack(f0[j], f1[j], h, l);   // pack over k: row 2kp even
                int ib = IDXA(n4 + j, kp);
                Bhi[ib] = h; Blo[ib] = l;
            }
        }
        __syncthreads();

#pragma unroll
        for (int ks = 0; ks < 2; ++ks) {          // two k16 steps
            unsigned ah[2][4], al[2][4];
#pragma unroll
            for (int t = 0; t < 2; ++t) {
                int r0 = wm + t * 16 + g;
                ah[t][0] = Ahi[IDXA(r0,     ks * 8 + tig)];
                ah[t][1] = Ahi[IDXA(r0 + 8, ks * 8 + tig)];
                ah[t][2] = Ahi[IDXA(r0,     ks * 8 + tig + 4)];
                ah[t][3] = Ahi[IDXA(r0 + 8, ks * 8 + tig + 4)];
                al[t][0] = Alo[IDXA(r0,     ks * 8 + tig)];
                al[t][1] = Alo[IDXA(r0 + 8, ks * 8 + tig)];
                al[t][2] = Alo[IDXA(r0,     ks * 8 + tig + 4)];
                al[t][3] = Alo[IDXA(r0 + 8, ks * 8 + tig + 4)];
            }
#pragma unroll
            for (int u = 0; u < 4; ++u) {
                int n = wn + u * 8 + g;
                unsigned bh[2] = { Bhi[IDXA(n, ks * 8 + tig)], Bhi[IDXA(n, ks * 8 + tig + 4)] };
                unsigned bl[2] = { Blo[IDXA(n, ks * 8 + tig)], Blo[IDXA(n, ks * 8 + tig + 4)] };
#pragma unroll
                for (int t = 0; t < 2; ++t) {
                    mma_bf16(acc[t][u], ah[t], bh);
                    mma_bf16(acc[t][u], al[t], bh);
                    mma_bf16(acc[t][u], ah[t], bl);
                }
            }
        }
    }

    // Epilogue: write packed hi/lo in split-head layout. head = blockIdx.x.
    const int h = blockIdx.x;
    const float qscale = isQ ? 0.125f : 1.0f;
#pragma unroll
    for (int t = 0; t < 2; ++t)
#pragma unroll
        for (int u = 0; u < 4; ++u) {
            int dcol = wn + u * 8 + 2 * tig;      // even
            float bx = bias[bn + dcol], by = bias[bn + dcol + 1];
            int m0 = bm + wm + t * 16 + g;
#pragma unroll
            for (int half = 0; half < 2; ++half) {
                int m = m0 + half * 8;
                int b_ = m >> 11, s_ = m & (SEQ - 1);
                float v0 = (acc[t][u][half * 2 + 0] + bx) * qscale;
                float v1 = (acc[t][u][half * 2 + 1] + by) * qscale;
                unsigned hi, lo;
                split_pack(v0, v1, hi, lo);
                size_t widx = ((size_t)((b_ * NHEADS + h) * SEQ + s_)) * 32 + (dcol >> 1);
                outHi[widx] = hi; outLo[widx] = lo;
            }
        }
}

// ---------------------------------------------------------------------------
// Flash attention. CTA = 64 q-rows x (b,h), 4 warps x 16 q-rows.
// Q hi/lo fragments live in registers the whole kernel (LDG once).
// K loaded packed-over-d -> B frags via LDS.32. V loaded as bf16[c][d] with
// 16B XOR swizzle -> B frags via ldmatrix.x4.trans. P never touches SMEM.
// ---------------------------------------------------------------------------
__global__ __launch_bounds__(128) void attn_kernel()
{
    __shared__ unsigned Khi[64 * 32], Klo[64 * 32];
    __shared__ unsigned Vhi[64 * 32], Vlo[64 * 32];   // bf16[64][64] each

    const int tid  = threadIdx.x;
    const int warp = tid >> 5, lane = tid & 31;
    const int g = lane >> 2, tig = lane & 3;
    const int qw = warp * 16;
    const int bh = blockIdx.y;
    const int q0 = blockIdx.x * 64;

    // Q fragments (pre-scaled by producer)
    unsigned qh[4][4], ql[4][4];
    {
        size_t r0 = ((size_t)bh * SEQ + q0 + qw + g) * 32;
        size_t r1 = r0 + 8 * 32;
#pragma unroll
        for (int ks = 0; ks < 4; ++ks) {
            qh[ks][0] = g_qhi[r0 + ks * 8 + tig];
            qh[ks][1] = g_qhi[r1 + ks * 8 + tig];
            qh[ks][2] = g_qhi[r0 + ks * 8 + tig + 4];
            qh[ks][3] = g_qhi[r1 + ks * 8 + tig + 4];
            ql[ks][0] = g_qlo[r0 + ks * 8 + tig];
            ql[ks][1] = g_qlo[r1 + ks * 8 + tig];
            ql[ks][2] = g_qlo[r0 + ks * 8 + tig + 4];
            ql[ks][3] = g_qlo[r1 + ks * 8 + tig + 4];
        }
    }

    // ldmatrix lane constants
    const int sub = lane >> 3, ro = lane & 7;
    const int laneRow  = ((sub & 1) << 3) + ro;
    const int laneColW = (sub >> 1) << 2;     // words
    const int swzW     = ro << 2;             // word-granular 16B XOR
    const unsigned vbH = (unsigned)__cvta_generic_to_shared(Vhi);
    const unsigned vbL = (unsigned)__cvta_generic_to_shared(Vlo);

    float o[8][4] = {};
    float mrow[2] = {-1e30f, -1e30f};
    float lrow[2] = {0.f, 0.f};

#pragma unroll 1
    for (int kt = 0; kt < SEQ / 64; ++kt) {
        size_t base = ((size_t)bh * SEQ + kt * 64) * 32;

        __syncthreads();
#pragma unroll
        for (int it = 0; it < 4; ++it) {
            int idx = it * 128 + tid;
            int r = idx >> 3, wc = (idx & 7) * 4;
            int is = IDXK(r, wc);               // 4-word chunks stay contiguous
            *reinterpret_cast<uint4*>(&Khi[is]) =
                *reinterpret_cast<const uint4*>(&g_khi[base + r * 32 + wc]);
            *reinterpret_cast<uint4*>(&Klo[is]) =
                *reinterpret_cast<const uint4*>(&g_klo[base + r * 32 + wc]);
            *reinterpret_cast<uint4*>(&Vhi[is]) =
                *reinterpret_cast<const uint4*>(&g_vhi[base + r * 32 + wc]);
            *reinterpret_cast<uint4*>(&Vlo[is]) =
                *reinterpret_cast<const uint4*>(&g_vlo[base + r * 32 + wc]);
        }
        __syncthreads();

        // ---- scores: S = Q K^T (3-term) ----
        float s[8][4] = {};
#pragma unroll
        for (int ks = 0; ks < 4; ++ks) {
#pragma unroll
            for (int u = 0; u < 8; ++u) {
                int c = u * 8 + g;
                unsigned bh2[2] = { Khi[IDXK(c, ks * 8 + tig)], Khi[IDXK(c, ks * 8 + tig + 4)] };
                unsigned bl2[2] = { Klo[IDXK(c, ks * 8 + tig)], Klo[IDXK(c, ks * 8 + tig + 4)] };
                mma_bf16(s[u], qh[ks], bh2);
                mma_bf16(s[u], ql[ks], bh2);
                mma_bf16(s[u], qh[ks], bl2);
            }
        }

        // ---- online softmax ----
        float mx0 = -1e30f, mx1 = -1e30f;
#pragma unroll
        for (int u = 0; u < 8; ++u) {
            mx0 = fmaxf(mx0, fmaxf(s[u][0], s[u][1]));
            mx1 = fmaxf(mx1, fmaxf(s[u][2], s[u][3]));
        }
        mx0 = fmaxf(mx0, __shfl_xor_sync(0xffffffffu, mx0, 1));
        mx0 = fmaxf(mx0, __shfl_xor_sync(0xffffffffu, mx0, 2));
        mx1 = fmaxf(mx1, __shfl_xor_sync(0xffffffffu, mx1, 1));
        mx1 = fmaxf(mx1, __shfl_xor_sync(0xffffffffu, mx1, 2));

        float m0n = fmaxf(mrow[0], mx0), m1n = fmaxf(mrow[1], mx1);
        float a0 = __expf(mrow[0] - m0n), a1 = __expf(mrow[1] - m1n);
        mrow[0] = m0n; mrow[1] = m1n;

        float rs0 = 0.f, rs1 = 0.f;
#pragma unroll
        for (int u = 0; u < 8; ++u) {
            s[u][0] = __expf(s[u][0] - m0n); rs0 += s[u][0];
            s[u][1] = __expf(s[u][1] - m0n); rs0 += s[u][1];
            s[u][2] = __expf(s[u][2] - m1n); rs1 += s[u][2];
            s[u][3] = __expf(s[u][3] - m1n); rs1 += s[u][3];
        }
        rs0 += __shfl_xor_sync(0xffffffffu, rs0, 1);
        rs0 += __shfl_xor_sync(0xffffffffu, rs0, 2);
        rs1 += __shfl_xor_sync(0xffffffffu, rs1, 1);
        rs1 += __shfl_xor_sync(0xffffffffu, rs1, 2);
        lrow[0] = lrow[0] * a0 + rs0;
        lrow[1] = lrow[1] * a1 + rs1;

#pragma unroll
        for (int u = 0; u < 8; ++u) {
            o[u][0] *= a0; o[u][1] *= a0; o[u][2] *= a1; o[u][3] *= a1;
        }

        // ---- PV: O += P V  (P split in regs, V split via ldmatrix.trans) ----
#pragma unroll
        for (int ks = 0; ks < 4; ++ks) {
            unsigned ph[4], pl[4];                 // A-frag = softmax regs, repacked
            split_pack(s[2 * ks][0],     s[2 * ks][1],     ph[0], pl[0]);
            split_pack(s[2 * ks][2],     s[2 * ks][3],     ph[1], pl[1]);
            split_pack(s[2 * ks + 1][0], s[2 * ks + 1][1], ph[2], pl[2]);
            split_pack(s[2 * ks + 1][2], s[2 * ks + 1][3], ph[3], pl[3]);
            unsigned rowW = (unsigned)((ks * 16 + laneRow) << 5);
#pragma unroll
            for (int up = 0; up < 4; ++up) {
                unsigned cw = (unsigned)(((up << 3) + laneColW) ^ swzW);
                unsigned h0, h1, h2, h3, l0, l1, l2, l3;
                ldsm_x4_t(h0, h1, h2, h3, vbH + ((rowW + cw) << 2));
                ldsm_x4_t(l0, l1, l2, l3, vbL + ((rowW + cw) << 2));
                unsigned BH0[2] = {h0, h1}, BH1[2] = {h2, h3};
                unsigned BL0[2] = {l0, l1}, BL1[2] = {l2, l3};
                mma_bf16(o[2 * up],     ph, BH0);
                mma_bf16(o[2 * up],     pl, BH0);
                mma_bf16(o[2 * up],     ph, BL0);
                mma_bf16(o[2 * up + 1], ph, BH1);
                mma_bf16(o[2 * up + 1], pl, BH1);
                mma_bf16(o[2 * up + 1], ph, BL1);
            }
        }
    }

    // Epilogue: normalize, split, write packed attended [m][kp]
    const int b_ = bh >> 4, h = bh & 15;
    const float inv0 = 1.0f / lrow[0], inv1 = 1.0f / lrow[1];
    const size_t m0 = (size_t)(b_ * SEQ + q0 + qw + g);
    const size_t m1 = m0 + 8;
#pragma unroll
    for (int u = 0; u < 8; ++u) {
        int wcol = h * 32 + 4 * u + tig;            // word index of col pair
        unsigned hi, lo;
        split_pack(o[u][0] * inv0, o[u][1] * inv0, hi, lo);
        g_ahi[m0 * 512 + wcol] = hi; g_alo[m0 * 512 + wcol] = lo;
        split_pack(o[u][2] * inv1, o[u][3] * inv1, hi, lo);
        g_ahi[m1 * 512 + wcol] = hi; g_alo[m1 * 512 + wcol] = lo;
    }
}

// ---------------------------------------------------------------------------
// Output projection: out = attended @ Wo + bo. A comes pre-split (word copy);
// B (Wo) split at tile load. fp32 output.
// ---------------------------------------------------------------------------
__global__ __launch_bounds__(256) void out_gemm(
    const float* __restrict__ Wo, const float* __restrict__ bo,
    float* __restrict__ out)
{
    __shared__ unsigned Ahi[128 * 16], Alo[128 * 16];
    __shared__ unsigned Bhi[64 * 16],  Blo[64 * 16];

    const int tid  = threadIdx.x;
    const int warp = tid >> 5, lane = tid & 31;
    const int g = lane >> 2, tig = lane & 3;
    const int wm = (warp >> 1) * 32, wn = (warp & 1) * 32;
    const int bm = blockIdx.y * 128, bn = blockIdx.x * 64;

    const int am  = tid >> 1;
    const int dpb = (tid & 1) * 8;
    const int kp  = tid & 15;
    const int n4  = (tid >> 4) * 4;

    float acc[2][4][4] = {};

#pragma unroll 1
    for (int k0 = 0; k0 < D_MODEL; k0 += 32) {
        size_t arow = (size_t)(bm + am) * 512 + (k0 >> 1) + dpb;
        uint4 ah4 = *reinterpret_cast<const uint4*>(&g_ahi[arow]);
        uint4 ah5 = *reinterpret_cast<const uint4*>(&g_ahi[arow + 4]);
        uint4 al4 = *reinterpret_cast<const uint4*>(&g_alo[arow]);
        uint4 al5 = *reinterpret_cast<const uint4*>(&g_alo[arow + 4]);
        float4 b0 = *reinterpret_cast<const float4*>(Wo + (size_t)(k0 + 2 * kp) * D_MODEL + bn + n4);
        float4 b1 = *reinterpret_cast<const float4*>(Wo + (size_t)(k0 + 2 * kp + 1) * D_MODEL + bn + n4);

        __syncthreads();
        {
            int i0 = IDXA(am, dpb), i1 = IDXA(am, dpb + 4);   // 4-aligned quads
            *reinterpret_cast<uint4*>(&Ahi[i0]) = ah4;
            *reinterpret_cast<uint4*>(&Ahi[i1]) = ah5;
            *reinterpret_cast<uint4*>(&Alo[i0]) = al4;
            *reinterpret_cast<uint4*>(&Alo[i1]) = al5;
            const float* f0 = reinterpret_cast<const float*>(&b0);
            const float* f1 = reinterpret_cast<const float*>(&b1);
#pragma unroll
            for (int j = 0; j < 4; ++j) {
                unsigned h, l;
                split_pack(f0[j], f1[j], h, l);
                int ib = IDXA(n4 + j, kp);
                Bhi[ib] = h; Blo[ib] = l;
            }
        }
        __syncthreads();

#pragma unroll
        for (int ks = 0; ks < 2; ++ks) {
            unsigned ah[2][4], al[2][4];
#pragma unroll
            for (int t = 0; t < 2; ++t) {
                int r0 = wm + t * 16 + g;
                ah[t][0] = Ahi[IDXA(r0,     ks * 8 + tig)];
                ah[t][1] = Ahi[IDXA(r0 + 8, ks * 8 + tig)];
                ah[t][2] = Ahi[IDXA(r0,     ks * 8 + tig + 4)];
                ah[t][3] = Ahi[IDXA(r0 + 8, ks * 8 + tig + 4)];
                al[t][0] = Alo[IDXA(r0,     ks * 8 + tig)];
                al[t][1] = Alo[IDXA(r0 + 8, ks * 8 + tig)];
                al[t][2] = Alo[IDXA(r0,     ks * 8 + tig + 4)];
                al[t][3] = Alo[IDXA(r0 + 8, ks * 8 + tig + 4)];
            }
#pragma unroll
            for (int u = 0; u < 4; ++u) {
                int n = wn + u * 8 + g;
                unsigned bh[2] = { Bhi[IDXA(n, ks * 8 + tig)], Bhi[IDXA(n, ks * 8 + tig + 4)] };
                unsigned bl[2] = { Blo[IDXA(n, ks * 8 + tig)], Blo[IDXA(n, ks * 8 + tig + 4)] };
#pragma unroll
                for (int t = 0; t < 2; ++t) {
                    mma_bf16(acc[t][u], ah[t], bh);
                    mma_bf16(acc[t][u], al[t], bh);
                    mma_bf16(acc[t][u], ah[t], bl);
                }
            }
        }
    }

#pragma unroll
    for (int t = 0; t < 2; ++t)
#pragma unroll
        for (int u = 0; u < 4; ++u) {
            int dcol = wn + u * 8 + 2 * tig;
            float bx = bo[bn + dcol], by = bo[bn + dcol + 1];
            int m0 = bm + wm + t * 16 + g;
#pragma unroll
            for (int half = 0; half < 2; ++half) {
                int m = m0 + half * 8;
                float2 r;
                r.x = acc[t][u][half * 2 + 0] + bx;
                r.y = acc[t][u][half * 2 + 1] + by;
                *reinterpret_cast<float2*>(out + (size_t)m * D_MODEL + bn + dcol) = r;
            }
        }
}

// ---------------------------------------------------------------------------
extern "C" void kernel_launch(void* const* d_in, const int* in_sizes, int n_in,
                              void* d_out, int out_size)
{
    const float* x  = (const float*)d_in[0];
    const float* Wq = (const float*)d_in[1];
    const float* bq = (const float*)d_in[2];
    const float* Wk = (const float*)d_in[3];
    const float* bk = (const float*)d_in[4];
    const float* Wv = (const float*)d_in[5];
    const float* bv = (const float*)d_in[6];
    const float* Wo = (const float*)d_in[7];
    const float* bo = (const float*)d_in[8];
    float* out = (float*)d_out;

    dim3 g1(D_MODEL / 64, MTOT / 128, 3);
    qkv_gemm<<<g1, 256>>>(x, Wq, bq, Wk, bk, Wv, bv);

    dim3 g2(SEQ / 64, BATCH * NHEADS);
    attn_kernel<<<g2, 128>>>();

    dim3 g3(D_MODEL / 64, MTOT / 128);
    out_gemm<<<g3, 256>>>(Wo, bo, out);
}